// round 5
// baseline (speedup 1.0000x reference)
#include <cuda_runtime.h>
#include <math.h>

#define Bz 64
#define Sz 128
#define Hz 1024
#define Az 512
#define Vz 32001
#define Tz 32
#define G4 4096

// ---------------- scratch (static device globals; no allocation) ----------------
__device__ float g_Xg[(size_t)Sz * Bz * G4];     // [t][b][4H] reordered-gate layout
__device__ float g_enc[(size_t)Sz * Bz * Hz];    // [t][b][H]
__device__ float g_s1[(size_t)Sz * Bz * Az];     // [s][b][A]
__device__ float g_WihRe[(size_t)G4 * Hz];       // gate-reordered weights
__device__ float g_WhhRe[(size_t)G4 * Hz];
__device__ float g_WihRd[(size_t)G4 * 2 * Hz];
__device__ float g_WhhRd[(size_t)G4 * Hz];
__device__ float g_h[Bz * Hz];
__device__ float g_c[Bz * Hz];
__device__ float g_hd[Bz * Hz];
__device__ float g_ctx[Bz * Hz];
__device__ float g_dconst[Bz * G4];              // reordered layout
__device__ float g_s2[Bz * Az];
__device__ float g_beR[G4];
__device__ float g_bdR[G4];
__device__ int   g_tok[Bz];
__device__ int   g_is64[2];

__device__ __forceinline__ float sigm(float x) { return 1.0f / (1.0f + expf(-x)); }

__device__ __forceinline__ unsigned f2tf32(float x) {
    unsigned r;
    asm("cvt.rna.tf32.f32 %0, %1;" : "=r"(r) : "f"(x));
    return r;
}

__device__ __forceinline__ void mma8(float* c, const unsigned* a, const unsigned* b) {
    asm volatile(
        "mma.sync.aligned.m16n8k8.row.col.f32.tf32.tf32.f32 "
        "{%0,%1,%2,%3},{%4,%5,%6,%7},{%8,%9},{%0,%1,%2,%3};"
        : "+f"(c[0]), "+f"(c[1]), "+f"(c[2]), "+f"(c[3])
        : "r"(a[0]), "r"(a[1]), "r"(a[2]), "r"(a[3]), "r"(b[0]), "r"(b[1]));
}

// ---------------- int64-vs-int32 detection ----------------------------------------
__global__ void k_detect(const int* __restrict__ enc_tok, const int* __restrict__ dec_tok) {
    __shared__ int f0, f1;
    if (threadIdx.x == 0) { f0 = 0; f1 = 0; }
    __syncthreads();
    for (int i = threadIdx.x; i < Bz * Sz / 2; i += blockDim.x)
        if (enc_tok[2 * i + 1] != 0) atomicOr(&f0, 1);
    for (int i = threadIdx.x; i < Bz / 2; i += blockDim.x)
        if (dec_tok[2 * i + 1] != 0) atomicOr(&f1, 1);
    __syncthreads();
    if (threadIdx.x == 0) { g_is64[0] = f0 ? 0 : 1; g_is64[1] = f1 ? 0 : 1; }
}

// ---------------- init: reordered biases, states, tokens --------------------------
__global__ void k_init(const float* __restrict__ bih_e, const float* __restrict__ bhh_e,
                       const float* __restrict__ bih_d, const float* __restrict__ bhh_d,
                       const float* __restrict__ init_ctx, const int* __restrict__ dec_tok) {
    int i = blockIdx.x * blockDim.x + threadIdx.x;
    if (i < G4) {
        int u = i >> 2, g = i & 3;
        int src = g * Hz + u;
        g_beR[i] = bih_e[src] + bhh_e[src];
        g_bdR[i] = bih_d[src] + bhh_d[src];
    }
    if (i < Bz * Hz) { g_h[i] = 0.0f; g_c[i] = 0.0f; g_ctx[i] = init_ctx[i]; }
    if (i < Bz) g_tok[i] = g_is64[1] ? dec_tok[2 * i] : dec_tok[i];
}

// ---------------- weight gate-reorder: Wr[4u+g][k] = W[g*1024+u][k] ---------------
__global__ void k_reorder(const float* __restrict__ W, float* __restrict__ Wr, int ldw) {
    int np = blockIdx.x;                 // 0..4095
    int u = np >> 2, g = np & 3;
    const float* src = W + ((size_t)g * Hz + u) * ldw;
    float* dst = Wr + (size_t)np * ldw;
    for (int k = threadIdx.x * 4; k < ldw; k += blockDim.x * 4)
        *(float4*)(dst + k) = *(const float4*)(src + k);
}

// ---------------- 3xTF32 tensor-core GEMM: out = A[Mx K] * W[N x K]^T -------------
// BM=64, BN=64, BK=32; 128 threads = 4 warps (2M x 2N), warp tile 32x32.
// AMODE: 0 plain A(lda); 1 encoder token gather; 2 decoder concat [emb|ctx] (K=2048)
// EPI:   0 +bias -> out (N-guarded); 2 fused encoder LSTM cell; 3 fused decoder cell
union SMem {
    struct { float Ah[64][36]; float Al[64][36]; float Wt[64][36]; } t;
    float Cs[64][68];
};

template <int AMODE, int EPI>
__global__ void __launch_bounds__(128) k_mm(
    const float* __restrict__ A, int lda,
    const float* __restrict__ W, int ldw,
    const float* __restrict__ bias,
    const float* __restrict__ addC, int ldc,
    float* __restrict__ out, int ldo,
    int N, int K,
    const int* __restrict__ tok32, const float* __restrict__ emb,
    int t_step) {
    __shared__ SMem sm;
    const int tid = threadIdx.x;
    const int lane = tid & 31, warp = tid >> 5;
    const int wm = (warp & 1) * 32, wn = (warp >> 1) * 32;
    const int gid = lane >> 2, tig = lane & 3;
    const int bn = blockIdx.x * 64;
    const int bm = blockIdx.y * 64;

    const int ar = tid >> 1;            // tile row handled by this thread (0..63)
    const int ko = (tid & 1) * 16;      // k-offset within BK

    const float* aptr;
    const float* aptr2 = nullptr;
    if (AMODE == 0) {
        aptr = A + (size_t)(bm + ar) * lda;
    } else if (AMODE == 1) {
        int gm = bm + ar;
        int b = gm & 63, tt = gm >> 6;
        int idx = b * Sz + tt;
        int token = g_is64[0] ? tok32[2 * idx] : tok32[idx];
        aptr = emb + (size_t)token * Hz;
    } else {
        aptr = emb + (size_t)g_tok[ar] * Hz;   // emb_dec row
        aptr2 = g_ctx + (size_t)ar * Hz;       // context row
    }
    const int wr = bn + ar;
    const float* wptr = W + (size_t)wr * ldw;
    const bool wvalid = (wr < N);

    float acc[2][4][4];
#pragma unroll
    for (int mt = 0; mt < 2; mt++)
#pragma unroll
        for (int nt = 0; nt < 4; nt++)
#pragma unroll
            for (int q = 0; q < 4; q++) acc[mt][nt][q] = 0.0f;

    float4 sa[4], sw[4];

    // prologue loads (k0 = 0)
    {
        const float* p = (AMODE == 2 && 0 >= Hz) ? aptr2 : aptr;  // k0=0 < Hz always
        p = aptr + ko;
#pragma unroll
        for (int q = 0; q < 4; q++) sa[q] = *(const float4*)(p + q * 4);
        if (wvalid) {
            const float* wp = wptr + ko;
#pragma unroll
            for (int q = 0; q < 4; q++) sw[q] = *(const float4*)(wp + q * 4);
        } else {
#pragma unroll
            for (int q = 0; q < 4; q++) sw[q] = make_float4(0.f, 0.f, 0.f, 0.f);
        }
    }

    for (int k0 = 0; k0 < K; k0 += 32) {
        __syncthreads();
        // store staging -> smem; A split into tf32 hi/lo at store
#pragma unroll
        for (int q = 0; q < 4; q++) {
            float v[4] = {sa[q].x, sa[q].y, sa[q].z, sa[q].w};
            int kb = ko + q * 4;
#pragma unroll
            for (int j = 0; j < 4; j++) {
                unsigned h = f2tf32(v[j]);
                float hf = __uint_as_float(h);
                unsigned l = f2tf32(v[j] - hf);
                sm.t.Ah[ar][kb + j] = hf;
                sm.t.Al[ar][kb + j] = __uint_as_float(l);
            }
        }
#pragma unroll
        for (int q = 0; q < 4; q++) {
            int kb = ko + q * 4;
            sm.t.Wt[ar][kb + 0] = sw[q].x;
            sm.t.Wt[ar][kb + 1] = sw[q].y;
            sm.t.Wt[ar][kb + 2] = sw[q].z;
            sm.t.Wt[ar][kb + 3] = sw[q].w;
        }
        __syncthreads();

        // prefetch next k-tile
        int kn = k0 + 32;
        if (kn < K) {
            const float* p;
            if (AMODE == 2) p = (kn < Hz) ? (aptr + kn) : (aptr2 + (kn - Hz));
            else p = aptr + kn;
            p += ko;
#pragma unroll
            for (int q = 0; q < 4; q++) sa[q] = *(const float4*)(p + q * 4);
            if (wvalid) {
                const float* wp = wptr + kn + ko;
#pragma unroll
                for (int q = 0; q < 4; q++) sw[q] = *(const float4*)(wp + q * 4);
            }
        }

        // compute 4 k8 steps
#pragma unroll
        for (int k8 = 0; k8 < 4; k8++) {
            const int kk = k8 * 8;
            unsigned ah[2][4], al[2][4];
#pragma unroll
            for (int mt = 0; mt < 2; mt++) {
                int r0 = wm + mt * 16 + gid;
                ah[mt][0] = __float_as_uint(sm.t.Ah[r0][kk + tig]);
                ah[mt][1] = __float_as_uint(sm.t.Ah[r0 + 8][kk + tig]);
                ah[mt][2] = __float_as_uint(sm.t.Ah[r0][kk + tig + 4]);
                ah[mt][3] = __float_as_uint(sm.t.Ah[r0 + 8][kk + tig + 4]);
                al[mt][0] = __float_as_uint(sm.t.Al[r0][kk + tig]);
                al[mt][1] = __float_as_uint(sm.t.Al[r0 + 8][kk + tig]);
                al[mt][2] = __float_as_uint(sm.t.Al[r0][kk + tig + 4]);
                al[mt][3] = __float_as_uint(sm.t.Al[r0 + 8][kk + tig + 4]);
            }
            unsigned bh[4][2], bl[4][2];
#pragma unroll
            for (int nt = 0; nt < 4; nt++) {
                int n = wn + nt * 8 + gid;
                float x0 = sm.t.Wt[n][kk + tig];
                float x1 = sm.t.Wt[n][kk + tig + 4];
                unsigned h0 = f2tf32(x0), h1 = f2tf32(x1);
                bh[nt][0] = h0; bh[nt][1] = h1;
                bl[nt][0] = f2tf32(x0 - __uint_as_float(h0));
                bl[nt][1] = f2tf32(x1 - __uint_as_float(h1));
            }
            // pass 0: hi*hi
#pragma unroll
            for (int mt = 0; mt < 2; mt++)
#pragma unroll
                for (int nt = 0; nt < 4; nt++) mma8(acc[mt][nt], ah[mt], bh[nt]);
            // pass 1: hi*lo
#pragma unroll
            for (int mt = 0; mt < 2; mt++)
#pragma unroll
                for (int nt = 0; nt < 4; nt++) mma8(acc[mt][nt], ah[mt], bl[nt]);
            // pass 2: lo*hi
#pragma unroll
            for (int mt = 0; mt < 2; mt++)
#pragma unroll
                for (int nt = 0; nt < 4; nt++) mma8(acc[mt][nt], al[mt], bh[nt]);
        }
    }

    if (EPI == 0) {
#pragma unroll
        for (int mt = 0; mt < 2; mt++) {
            int row0 = bm + wm + mt * 16 + gid;
#pragma unroll
            for (int nt = 0; nt < 4; nt++) {
                int col = bn + wn + nt * 8 + 2 * tig;
                if (col < N) {
                    float b0 = bias[col];
                    out[(size_t)row0 * ldo + col] = acc[mt][nt][0] + b0;
                    out[(size_t)(row0 + 8) * ldo + col] = acc[mt][nt][2] + b0;
                }
                if (col + 1 < N) {
                    float b1 = bias[col + 1];
                    out[(size_t)row0 * ldo + col + 1] = acc[mt][nt][1] + b1;
                    out[(size_t)(row0 + 8) * ldo + col + 1] = acc[mt][nt][3] + b1;
                }
            }
        }
    } else {
        // fused LSTM cell epilogue (EPI 2 encoder / EPI 3 decoder)
        __syncthreads();
#pragma unroll
        for (int mt = 0; mt < 2; mt++) {
            int lr0 = wm + mt * 16 + gid;
#pragma unroll
            for (int nt = 0; nt < 4; nt++) {
                int lc = wn + nt * 8 + 2 * tig;
                sm.Cs[lr0][lc] = acc[mt][nt][0];
                sm.Cs[lr0][lc + 1] = acc[mt][nt][1];
                sm.Cs[lr0 + 8][lc] = acc[mt][nt][2];
                sm.Cs[lr0 + 8][lc + 1] = acc[mt][nt][3];
            }
        }
        __syncthreads();
#pragma unroll
        for (int e = 0; e < 8; e++) {
            int idx = tid + e * 128;         // 0..1023
            int row = idx >> 4;              // 0..63
            int u = idx & 15;                // 0..15 (unit within block)
            float4 ad = *(const float4*)(addC + (size_t)row * ldc + bn + 4 * u);
            float ig = sm.Cs[row][4 * u + 0] + ad.x;
            float fg = sm.Cs[row][4 * u + 1] + ad.y;
            float gg = sm.Cs[row][4 * u + 2] + ad.z;
            float og = sm.Cs[row][4 * u + 3] + ad.w;
            int ug = (bn >> 2) + u;          // global unit index
            float cold = g_c[row * Hz + ug];
            float cn = sigm(fg) * cold + sigm(ig) * tanhf(gg);
            float h = sigm(og) * tanhf(cn);
            if (EPI == 2) {
                g_c[row * Hz + ug] = cn;
                g_h[row * Hz + ug] = h;
                g_enc[(size_t)t_step * Bz * Hz + row * Hz + ug] = h;
            } else {
                g_hd[row * Hz + ug] = h;
            }
        }
    }
}

// ---------------- narrow fp32 SIMT GEMM for s2 = hd @ Wd^T + bd -------------------
__global__ void __launch_bounds__(128) k_gemm32(
    const float* __restrict__ A, int lda,
    const float* __restrict__ W, int ldw,
    const float* __restrict__ bias,
    float* __restrict__ out, int ldo,
    int N, int K) {
    __shared__ float As[16][68];
    __shared__ float Bs[16][36];
    const int tid = threadIdx.x;
    const int r0 = tid >> 2;
    const int r1 = r0 + 32;
    const int kq = (tid & 3) << 2;
    const int bn = blockIdx.x << 5;

    const float* arow0 = A + (size_t)r0 * lda;
    const float* arow1 = A + (size_t)r1 * lda;
    const float* wrow = W + (size_t)(bn + r0) * ldw;

    float acc[4][4];
#pragma unroll
    for (int i = 0; i < 4; i++)
#pragma unroll
        for (int j = 0; j < 4; j++) acc[i][j] = 0.0f;

    const int ty = tid >> 3;
    const int tx = tid & 7;

    for (int k0 = 0; k0 < K; k0 += 16) {
        float4 a0 = *(const float4*)(arow0 + k0 + kq);
        float4 a1 = *(const float4*)(arow1 + k0 + kq);
        float4 wv = *(const float4*)(wrow + k0 + kq);
        __syncthreads();
        As[kq + 0][r0] = a0.x; As[kq + 1][r0] = a0.y; As[kq + 2][r0] = a0.z; As[kq + 3][r0] = a0.w;
        As[kq + 0][r1] = a1.x; As[kq + 1][r1] = a1.y; As[kq + 2][r1] = a1.z; As[kq + 3][r1] = a1.w;
        Bs[kq + 0][r0] = wv.x; Bs[kq + 1][r0] = wv.y; Bs[kq + 2][r0] = wv.z; Bs[kq + 3][r0] = wv.w;
        __syncthreads();
#pragma unroll
        for (int kk = 0; kk < 16; kk++) {
            float4 a = *(const float4*)(&As[kk][ty << 2]);
            float4 b = *(const float4*)(&Bs[kk][tx << 2]);
            acc[0][0] += a.x * b.x; acc[0][1] += a.x * b.y; acc[0][2] += a.x * b.z; acc[0][3] += a.x * b.w;
            acc[1][0] += a.y * b.x; acc[1][1] += a.y * b.y; acc[1][2] += a.y * b.z; acc[1][3] += a.y * b.w;
            acc[2][0] += a.z * b.x; acc[2][1] += a.z * b.y; acc[2][2] += a.z * b.z; acc[2][3] += a.z * b.w;
            acc[3][0] += a.w * b.x; acc[3][1] += a.w * b.y; acc[3][2] += a.w * b.z; acc[3][3] += a.w * b.w;
        }
    }
    const int om = ty << 2;
    const int on = bn + (tx << 2);
#pragma unroll
    for (int i = 0; i < 4; i++) {
        float* orow = out + (size_t)(om + i) * ldo;
#pragma unroll
        for (int j = 0; j < 4; j++) {
            int c = on + j;
            if (c < N) orow[c] = acc[i][j] + bias[c];
        }
    }
}

// ---------------- attention: scores + softmax + context ---------------------------
__global__ void __launch_bounds__(256) k_attn(const float* __restrict__ Wv, const float* __restrict__ bv) {
    int b = blockIdx.x;
    __shared__ float s2s[Az];
    __shared__ float sc[Sz];
    __shared__ float red[8];
    int tid = threadIdx.x;
    int w = tid >> 5, l = tid & 31;
    for (int a = tid; a < Az; a += 256) s2s[a] = g_s2[b * Az + a];
    __syncthreads();
    for (int s = w; s < Sz; s += 8) {
        const float* row = g_s1 + ((size_t)s * Bz + b) * Az;
        float acc = 0.0f;
        for (int a = l; a < Az; a += 32) acc += tanhf(row[a] + s2s[a]) * Wv[a];
        for (int o = 16; o; o >>= 1) acc += __shfl_xor_sync(0xffffffffu, acc, o);
        if (l == 0) sc[s] = acc + bv[0];
    }
    __syncthreads();
    float m = -3.402823e38f;
    if (tid < Sz) m = sc[tid];
    for (int o = 16; o; o >>= 1) m = fmaxf(m, __shfl_xor_sync(0xffffffffu, m, o));
    if (l == 0) red[w] = m;
    __syncthreads();
    m = fmaxf(fmaxf(fmaxf(red[0], red[1]), fmaxf(red[2], red[3])),
              fmaxf(fmaxf(red[4], red[5]), fmaxf(red[6], red[7])));
    __syncthreads();
    float part = 0.0f;
    if (tid < Sz) { float e = expf(sc[tid] - m); sc[tid] = e; part = e; }
    for (int o = 16; o; o >>= 1) part += __shfl_xor_sync(0xffffffffu, part, o);
    if (l == 0) red[w] = part;
    __syncthreads();
    float inv = 1.0f / (red[0] + red[1] + red[2] + red[3] + red[4] + red[5] + red[6] + red[7]);
    for (int u = tid; u < Hz; u += 256) {
        float acc = 0.0f;
        for (int s = 0; s < Sz; s++) acc += sc[s] * g_enc[((size_t)s * Bz + b) * Hz + u];
        g_ctx[b * Hz + u] = acc * inv;
    }
}

// ---------------- argmax (first-occurrence tie-break) -----------------------------
__global__ void __launch_bounds__(256) k_argmax(const float* __restrict__ out, int t) {
    int b = blockIdx.x;
    const float* lg = out + (size_t)b * Tz * Vz + (size_t)t * Vz;
    int tid = threadIdx.x;
    float bm = -3.402823e38f;
    int bi = Vz;
    for (int v = tid; v < Vz; v += 256) {
        float x = lg[v];
        if (x > bm) { bm = x; bi = v; }
        else if (x == bm && v < bi) bi = v;
    }
    __shared__ float sv[256];
    __shared__ int si[256];
    sv[tid] = bm; si[tid] = bi;
    __syncthreads();
    for (int o = 128; o; o >>= 1) {
        if (tid < o) {
            if (sv[tid + o] > sv[tid] || (sv[tid + o] == sv[tid] && si[tid + o] < si[tid])) {
                sv[tid] = sv[tid + o]; si[tid] = si[tid + o];
            }
        }
        __syncthreads();
    }
    if (tid == 0) g_tok[b] = si[0];
}

// ---------------- host orchestration ---------------------------------------------
extern "C" void kernel_launch(void* const* d_in, const int* in_sizes, int n_in,
                              void* d_out, int out_size) {
    const int*   in_enc   = (const int*)d_in[0];
    const float* init_ctx = (const float*)d_in[1];
    const int*   in_dec   = (const int*)d_in[2];
    const float* emb_enc  = (const float*)d_in[3];
    const float* emb_dec  = (const float*)d_in[4];
    const float* Wih_e    = (const float*)d_in[5];
    const float* Whh_e    = (const float*)d_in[6];
    const float* bih_e    = (const float*)d_in[7];
    const float* bhh_e    = (const float*)d_in[8];
    const float* Wih_d    = (const float*)d_in[9];
    const float* Whh_d    = (const float*)d_in[10];
    const float* bih_d    = (const float*)d_in[11];
    const float* bhh_d    = (const float*)d_in[12];
    const float* We       = (const float*)d_in[13];
    const float* be       = (const float*)d_in[14];
    const float* Wd       = (const float*)d_in[15];
    const float* bd       = (const float*)d_in[16];
    const float* Wv       = (const float*)d_in[17];
    const float* bv       = (const float*)d_in[18];
    const float* Wout     = (const float*)d_in[19];
    const float* bout     = (const float*)d_in[20];
    float* out = (float*)d_out;

    float *pXg, *pEnc, *pS1, *pH, *pDconst, *pHd, *pS2, *pBeR, *pBdR;
    float *pWihRe, *pWhhRe, *pWihRd, *pWhhRd;
    cudaGetSymbolAddress((void**)&pXg, g_Xg);
    cudaGetSymbolAddress((void**)&pEnc, g_enc);
    cudaGetSymbolAddress((void**)&pS1, g_s1);
    cudaGetSymbolAddress((void**)&pH, g_h);
    cudaGetSymbolAddress((void**)&pDconst, g_dconst);
    cudaGetSymbolAddress((void**)&pHd, g_hd);
    cudaGetSymbolAddress((void**)&pS2, g_s2);
    cudaGetSymbolAddress((void**)&pBeR, g_beR);
    cudaGetSymbolAddress((void**)&pBdR, g_bdR);
    cudaGetSymbolAddress((void**)&pWihRe, g_WihRe);
    cudaGetSymbolAddress((void**)&pWhhRe, g_WhhRe);
    cudaGetSymbolAddress((void**)&pWihRd, g_WihRd);
    cudaGetSymbolAddress((void**)&pWhhRd, g_WhhRd);

    k_detect<<<1, 256>>>(in_enc, in_dec);
    k_init<<<256, 256>>>(bih_e, bhh_e, bih_d, bhh_d, init_ctx, in_dec);

    // one-time gate reorder of recurrent/input weights
    k_reorder<<<G4, 128>>>(Wih_e, pWihRe, Hz);
    k_reorder<<<G4, 128>>>(Whh_e, pWhhRe, Hz);
    k_reorder<<<G4, 128>>>(Wih_d, pWihRd, 2 * Hz);
    k_reorder<<<G4, 128>>>(Whh_d, pWhhRd, Hz);

    // Xg[t*B+b][4u+g] = emb_enc[tok(b,t)] @ WihRe^T + beR   (tensor, 3xTF32)
    k_mm<1, 0><<<dim3(G4 / 64, (Sz * Bz) / 64), 128>>>(
        nullptr, 0, pWihRe, Hz, pBeR, nullptr, 0,
        pXg, G4, G4, Hz, in_enc, emb_enc, 0);

    // encoder recurrence: fused GEMM + LSTM cell, one kernel per step
    for (int t = 0; t < Sz; t++) {
        k_mm<0, 2><<<dim3(G4 / 64, 1), 128>>>(
            pH, Hz, pWhhRe, Hz, nullptr, pXg + (size_t)t * Bz * G4, G4,
            nullptr, 0, G4, Hz, nullptr, nullptr, t);
    }

    // s1 = enc @ We^T + be   [S*B, A]
    k_mm<0, 0><<<dim3(Az / 64, (Sz * Bz) / 64), 128>>>(
        pEnc, Hz, We, Hz, be, nullptr, 0,
        pS1, Az, Az, Hz, nullptr, nullptr, 0);

    // decoder constant gates (reordered): hN @ WhhRd^T + bdR
    k_mm<0, 0><<<dim3(G4 / 64, 1), 128>>>(
        pH, Hz, pWhhRd, Hz, pBdR, nullptr, 0,
        pDconst, G4, G4, Hz, nullptr, nullptr, 0);

    // autoregressive decoder
    for (int t = 0; t < Tz; t++) {
        // fused: gates = dconst + [emb;ctx] @ WihRd^T, then cell -> g_hd
        k_mm<2, 3><<<dim3(G4 / 64, 1), 128>>>(
            nullptr, 0, pWihRd, 2 * Hz, nullptr, pDconst, G4,
            nullptr, 0, G4, 2 * Hz, nullptr, emb_dec, 0);
        // s2 = hd @ Wd^T + bd  (fp32 SIMT, small)
        k_gemm32<<<dim3(Az / 32, 1), 128>>>(pHd, Hz, Wd, Hz, bd, pS2, Az, Az, Hz);
        k_attn<<<Bz, 256>>>(Wv, bv);
        // logits = hd @ Wout^T + bout -> out[b][t][:]
        k_mm<0, 0><<<dim3((Vz + 63) / 64, 1), 128>>>(
            pHd, Hz, Wout, Hz, bout, nullptr, 0,
            out + (size_t)t * Vz, Tz * Vz, Vz, Hz, nullptr, nullptr, 0);
        k_argmax<<<Bz, 256>>>(out, t);
    }
}

// round 7
// speedup vs baseline: 1.0458x; 1.0458x over previous
#include <cuda_runtime.h>
#include <math.h>

#define Bz 64
#define Sz 128
#define Hz 1024
#define Az 512
#define Vz 32001
#define Tz 32
#define G4 4096

// ---------------- scratch (static device globals; no allocation) ----------------
__device__ float g_Xg[(size_t)Sz * Bz * G4];     // [t][b][4H] reordered-gate layout
__device__ float g_enc[(size_t)Sz * Bz * Hz];    // [t][b][H]
__device__ float g_s1[(size_t)Sz * Bz * Az];     // [s][b][A]
__device__ float g_WihRe[(size_t)G4 * Hz];       // gate-reordered weights
__device__ float g_WhhRe[(size_t)G4 * Hz];
__device__ float g_WihRd[(size_t)G4 * 2 * Hz];
__device__ float g_WhhRd[(size_t)G4 * Hz];
__device__ float g_h[Bz * Hz];
__device__ float g_c[Bz * Hz];
__device__ float g_hd[Bz * Hz];
__device__ float g_ctx[Bz * Hz];
__device__ float g_dconst[Bz * G4];              // reordered layout
__device__ float g_s2[Bz * Az];
__device__ float g_beR[G4];
__device__ float g_bdR[G4];
__device__ int   g_tok[Bz];
__device__ int   g_is64[2];

__device__ __forceinline__ float sigm(float x) { return 1.0f / (1.0f + expf(-x)); }

__device__ __forceinline__ float tf32r(float x) {
    unsigned r;
    asm("cvt.rna.tf32.f32 %0, %1;" : "=r"(r) : "f"(x));
    return __uint_as_float(r);
}

__device__ __forceinline__ void mma8(float* c, const float4& a, const float2& b) {
    asm volatile(
        "mma.sync.aligned.m16n8k8.row.col.f32.tf32.tf32.f32 "
        "{%0,%1,%2,%3},{%4,%5,%6,%7},{%8,%9},{%0,%1,%2,%3};"
        : "+f"(c[0]), "+f"(c[1]), "+f"(c[2]), "+f"(c[3])
        : "r"(__float_as_uint(a.x)), "r"(__float_as_uint(a.y)),
          "r"(__float_as_uint(a.z)), "r"(__float_as_uint(a.w)),
          "r"(__float_as_uint(b.x)), "r"(__float_as_uint(b.y)));
}

__device__ __forceinline__ int swz(int u) { return u ^ ((u >> 3) & 7); }

// ---------------- int64-vs-int32 detection ----------------------------------------
__global__ void k_detect(const int* __restrict__ enc_tok, const int* __restrict__ dec_tok) {
    __shared__ int f0, f1;
    if (threadIdx.x == 0) { f0 = 0; f1 = 0; }
    __syncthreads();
    for (int i = threadIdx.x; i < Bz * Sz / 2; i += blockDim.x)
        if (enc_tok[2 * i + 1] != 0) atomicOr(&f0, 1);
    for (int i = threadIdx.x; i < Bz / 2; i += blockDim.x)
        if (dec_tok[2 * i + 1] != 0) atomicOr(&f1, 1);
    __syncthreads();
    if (threadIdx.x == 0) { g_is64[0] = f0 ? 0 : 1; g_is64[1] = f1 ? 0 : 1; }
}

// ---------------- init ------------------------------------------------------------
__global__ void k_init(const float* __restrict__ bih_e, const float* __restrict__ bhh_e,
                       const float* __restrict__ bih_d, const float* __restrict__ bhh_d,
                       const float* __restrict__ init_ctx, const int* __restrict__ dec_tok) {
    int i = blockIdx.x * blockDim.x + threadIdx.x;
    if (i < G4) {
        int u = i >> 2, g = i & 3;
        int src = g * Hz + u;
        g_beR[i] = bih_e[src] + bhh_e[src];
        g_bdR[i] = bih_d[src] + bhh_d[src];
    }
    if (i < Bz * Hz) { g_h[i] = 0.0f; g_c[i] = 0.0f; g_ctx[i] = init_ctx[i]; }
    if (i < Bz) g_tok[i] = g_is64[1] ? dec_tok[2 * i] : dec_tok[i];
}

// ---------------- weight gate-reorder: Wr[4u+g][k] = W[g*1024+u][k] ---------------
__global__ void k_reorder(const float* __restrict__ W, float* __restrict__ Wr, int ldw) {
    int np = blockIdx.x;
    int u = np >> 2, g = np & 3;
    const float* src = W + ((size_t)g * Hz + u) * ldw;
    float* dst = Wr + (size_t)np * ldw;
    for (int k = threadIdx.x * 4; k < ldw; k += blockDim.x * 4)
        *(float4*)(dst + k) = *(const float4*)(src + k);
}

// ---------------- 3xTF32 tensor GEMM, fragment-order smem -------------------------
// BM=64, BN=32, BK=32; 128 threads = 4 warps in (2M x 2N); warp tile 32x16.
// AMODE: 0 plain A(lda); 1 encoder token gather; 2 decoder concat [emb|ctx] (K=2048)
// EPI:   0 +bias->out (N-guarded); 2 fused encoder LSTM cell; 3 fused decoder cell
union SMem {
    struct {
        float AhF[4 * 512];   // [mtile 4][phys-unit 128][frag 4]
        float AlF[4 * 512];
        float BhF[4 * 256];   // [ntile 4][phys-unit 128][half 2]
        float BlF[4 * 256];
    } t;
    float Cs[64 * 33];
};

template <int AMODE, int EPI>
__global__ void __launch_bounds__(128) k_mm(
    const float* __restrict__ A, int lda,
    const float* __restrict__ W, int ldw,
    const float* __restrict__ bias,
    const float* __restrict__ addC, int ldc,
    float* __restrict__ out, int ldo,
    int N, int K,
    const int* __restrict__ tok32, const float* __restrict__ emb,
    int t_step) {
    __shared__ SMem sm;
    const int tid = threadIdx.x;
    const int lane = tid & 31, warp = tid >> 5;
    const int wmb = warp & 1, wnb = warp >> 1;
    const int mtb = wmb * 2, ntb = wnb * 2;
    const int gid = lane >> 2, tig = lane & 3;
    const int bn = blockIdx.x * 32;
    const int bm = blockIdx.y * 64;

    // staging roles
    const int ar = tid >> 1;             // A row 0..63
    const int ko = (tid & 1) * 16;       // A k-offset
    const int br = tid >> 2;             // B row 0..31
    const int kob = (tid & 3) * 8;       // B k-offset

    const float* aptr;
    const float* aptr2 = nullptr;
    if (AMODE == 0) {
        aptr = A + (size_t)(bm + ar) * lda;
    } else if (AMODE == 1) {
        int gm = bm + ar;
        int b = gm & 63, tt = gm >> 6;
        int idx = b * Sz + tt;
        int token = g_is64[0] ? tok32[2 * idx] : tok32[idx];
        aptr = emb + (size_t)token * Hz;
    } else {
        aptr = emb + (size_t)g_tok[ar] * Hz;
        aptr2 = g_ctx + (size_t)ar * Hz;
    }
    const int wr = bn + br;
    const float* wptr = W + (size_t)wr * ldw;
    const bool wvalid = (wr < N);

    float acc[2][2][4];
#pragma unroll
    for (int mt = 0; mt < 2; mt++)
#pragma unroll
        for (int nt = 0; nt < 2; nt++)
#pragma unroll
            for (int q = 0; q < 4; q++) acc[mt][nt][q] = 0.0f;

    float4 sa[4], sw[2];
    // prologue (k0 = 0)
    {
#pragma unroll
        for (int q = 0; q < 4; q++) sa[q] = *(const float4*)(aptr + ko + q * 4);
        if (wvalid) {
#pragma unroll
            for (int q = 0; q < 2; q++) sw[q] = *(const float4*)(wptr + kob + q * 4);
        } else {
            sw[0] = sw[1] = make_float4(0.f, 0.f, 0.f, 0.f);
        }
    }

    const int amt = ar >> 4;                 // A mtile of this staging thread
    const int afb = (ar >> 3) & 1;           // A frag base bit
    const int alane = (ar & 7) << 2;
    const int bnt = br >> 3;
    const int blane = (br & 7) << 2;

    for (int k0 = 0; k0 < K; k0 += 32) {
        __syncthreads();
        // ---- stage A (hi/lo split at store) ----
#pragma unroll
        for (int q = 0; q < 4; q++) {
            float v[4] = {sa[q].x, sa[q].y, sa[q].z, sa[q].w};
            int s = (tid & 1) * 2 + (q >> 1);
            int fb = afb | ((q & 1) << 1);
#pragma unroll
            for (int j = 0; j < 4; j++) {
                int p = swz(s * 32 + (alane | j));
                float hi = tf32r(v[j]);
                sm.t.AhF[amt * 512 + p * 4 + fb] = hi;
                sm.t.AlF[amt * 512 + p * 4 + fb] = tf32r(v[j] - hi);
            }
        }
        // ---- stage B ----
#pragma unroll
        for (int q = 0; q < 2; q++) {
            float v[4] = {sw[q].x, sw[q].y, sw[q].z, sw[q].w};
            int s = tid & 3;
#pragma unroll
            for (int j = 0; j < 4; j++) {
                int p = swz(s * 32 + (blane | j));
                float hi = tf32r(v[j]);
                sm.t.BhF[bnt * 256 + p * 2 + q] = hi;
                sm.t.BlF[bnt * 256 + p * 2 + q] = tf32r(v[j] - hi);
            }
        }
        __syncthreads();

        // ---- prefetch next tile ----
        int kn = k0 + 32;
        if (kn < K) {
            const float* p;
            if (AMODE == 2) p = (kn < Hz) ? (aptr + kn) : (aptr2 + (kn - Hz));
            else p = aptr + kn;
#pragma unroll
            for (int q = 0; q < 4; q++) sa[q] = *(const float4*)(p + ko + q * 4);
            if (wvalid) {
#pragma unroll
                for (int q = 0; q < 2; q++) sw[q] = *(const float4*)(wptr + kn + kob + q * 4);
            }
        }

        // ---- compute 4 k8-slabs ----
#pragma unroll
        for (int s = 0; s < 4; s++) {
            int p = swz(s * 32 + lane);
            float4 ah0 = *(const float4*)&sm.t.AhF[(mtb + 0) * 512 + p * 4];
            float4 ah1 = *(const float4*)&sm.t.AhF[(mtb + 1) * 512 + p * 4];
            float4 al0 = *(const float4*)&sm.t.AlF[(mtb + 0) * 512 + p * 4];
            float4 al1 = *(const float4*)&sm.t.AlF[(mtb + 1) * 512 + p * 4];
            float2 bh0 = *(const float2*)&sm.t.BhF[(ntb + 0) * 256 + p * 2];
            float2 bh1 = *(const float2*)&sm.t.BhF[(ntb + 1) * 256 + p * 2];
            float2 bl0 = *(const float2*)&sm.t.BlF[(ntb + 0) * 256 + p * 2];
            float2 bl1 = *(const float2*)&sm.t.BlF[(ntb + 1) * 256 + p * 2];
            mma8(acc[0][0], ah0, bh0); mma8(acc[0][1], ah0, bh1);
            mma8(acc[1][0], ah1, bh0); mma8(acc[1][1], ah1, bh1);
            mma8(acc[0][0], ah0, bl0); mma8(acc[0][1], ah0, bl1);
            mma8(acc[1][0], ah1, bl0); mma8(acc[1][1], ah1, bl1);
            mma8(acc[0][0], al0, bh0); mma8(acc[0][1], al0, bh1);
            mma8(acc[1][0], al1, bh0); mma8(acc[1][1], al1, bh1);
        }
    }

    if (EPI == 0) {
#pragma unroll
        for (int mt = 0; mt < 2; mt++) {
            int r0 = bm + wmb * 32 + mt * 16 + gid;
#pragma unroll
            for (int nt = 0; nt < 2; nt++) {
                int c0 = bn + wnb * 16 + nt * 8 + 2 * tig;
                if (c0 < N) {
                    float b0 = bias[c0];
                    out[(size_t)r0 * ldo + c0] = acc[mt][nt][0] + b0;
                    out[(size_t)(r0 + 8) * ldo + c0] = acc[mt][nt][2] + b0;
                }
                if (c0 + 1 < N) {
                    float b1 = bias[c0 + 1];
                    out[(size_t)r0 * ldo + c0 + 1] = acc[mt][nt][1] + b1;
                    out[(size_t)(r0 + 8) * ldo + c0 + 1] = acc[mt][nt][3] + b1;
                }
            }
        }
    } else {
        // fused LSTM cell (EPI 2 encoder / EPI 3 decoder); gates in cols bn..bn+31
        __syncthreads();
#pragma unroll
        for (int mt = 0; mt < 2; mt++) {
            int lr = wmb * 32 + mt * 16 + gid;
#pragma unroll
            for (int nt = 0; nt < 2; nt++) {
                int lc = wnb * 16 + nt * 8 + 2 * tig;
                sm.Cs[lr * 33 + lc] = acc[mt][nt][0];
                sm.Cs[lr * 33 + lc + 1] = acc[mt][nt][1];
                sm.Cs[(lr + 8) * 33 + lc] = acc[mt][nt][2];
                sm.Cs[(lr + 8) * 33 + lc + 1] = acc[mt][nt][3];
            }
        }
        __syncthreads();
#pragma unroll
        for (int e = 0; e < 4; e++) {
            int idx = tid + e * 128;      // 0..511
            int row = idx >> 3;           // 0..63
            int u = idx & 7;              // 0..7
            float4 ad = *(const float4*)(addC + (size_t)row * ldc + bn + 4 * u);
            float ig = sm.Cs[row * 33 + 4 * u + 0] + ad.x;
            float fg = sm.Cs[row * 33 + 4 * u + 1] + ad.y;
            float gg = sm.Cs[row * 33 + 4 * u + 2] + ad.z;
            float og = sm.Cs[row * 33 + 4 * u + 3] + ad.w;
            int ug = (bn >> 2) + u;
            float cold = g_c[row * Hz + ug];
            float cn = sigm(fg) * cold + sigm(ig) * tanhf(gg);
            float h = sigm(og) * tanhf(cn);
            if (EPI == 2) {
                g_c[row * Hz + ug] = cn;
                g_h[row * Hz + ug] = h;
                g_enc[(size_t)t_step * Bz * Hz + row * Hz + ug] = h;
            } else {
                g_hd[row * Hz + ug] = h;
            }
        }
    }
}

// ---------------- narrow fp32 SIMT GEMM for s2 = hd @ Wd^T + bd -------------------
__global__ void __launch_bounds__(128) k_gemm32(
    const float* __restrict__ A, int lda,
    const float* __restrict__ W, int ldw,
    const float* __restrict__ bias,
    float* __restrict__ out, int ldo,
    int N, int K) {
    __shared__ float As[16][68];
    __shared__ float Bs[16][36];
    const int tid = threadIdx.x;
    const int r0 = tid >> 2;
    const int r1 = r0 + 32;
    const int kq = (tid & 3) << 2;
    const int bn = blockIdx.x << 5;

    const float* arow0 = A + (size_t)r0 * lda;
    const float* arow1 = A + (size_t)r1 * lda;
    const float* wrow = W + (size_t)(bn + r0) * ldw;

    float acc[4][4];
#pragma unroll
    for (int i = 0; i < 4; i++)
#pragma unroll
        for (int j = 0; j < 4; j++) acc[i][j] = 0.0f;

    const int ty = tid >> 3;
    const int tx = tid & 7;

    for (int k0 = 0; k0 < K; k0 += 16) {
        float4 a0 = *(const float4*)(arow0 + k0 + kq);
        float4 a1 = *(const float4*)(arow1 + k0 + kq);
        float4 wv = *(const float4*)(wrow + k0 + kq);
        __syncthreads();
        As[kq + 0][r0] = a0.x; As[kq + 1][r0] = a0.y; As[kq + 2][r0] = a0.z; As[kq + 3][r0] = a0.w;
        As[kq + 0][r1] = a1.x; As[kq + 1][r1] = a1.y; As[kq + 2][r1] = a1.z; As[kq + 3][r1] = a1.w;
        Bs[kq + 0][r0] = wv.x; Bs[kq + 1][r0] = wv.y; Bs[kq + 2][r0] = wv.z; Bs[kq + 3][r0] = wv.w;
        __syncthreads();
#pragma unroll
        for (int kk = 0; kk < 16; kk++) {
            float4 a = *(const float4*)(&As[kk][ty << 2]);
            float4 b = *(const float4*)(&Bs[kk][tx << 2]);
            acc[0][0] += a.x * b.x; acc[0][1] += a.x * b.y; acc[0][2] += a.x * b.z; acc[0][3] += a.x * b.w;
            acc[1][0] += a.y * b.x; acc[1][1] += a.y * b.y; acc[1][2] += a.y * b.z; acc[1][3] += a.y * b.w;
            acc[2][0] += a.z * b.x; acc[2][1] += a.z * b.y; acc[2][2] += a.z * b.z; acc[2][3] += a.z * b.w;
            acc[3][0] += a.w * b.x; acc[3][1] += a.w * b.y; acc[3][2] += a.w * b.z; acc[3][3] += a.w * b.w;
        }
    }
    const int om = ty << 2;
    const int on = bn + (tx << 2);
#pragma unroll
    for (int i = 0; i < 4; i++) {
        float* orow = out + (size_t)(om + i) * ldo;
#pragma unroll
        for (int j = 0; j < 4; j++) {
            int c = on + j;
            if (c < N) orow[c] = acc[i][j] + bias[c];
        }
    }
}

// ---------------- attention: scores + softmax + context ---------------------------
__global__ void __launch_bounds__(256) k_attn(const float* __restrict__ Wv, const float* __restrict__ bv) {
    int b = blockIdx.x;
    __shared__ float s2s[Az];
    __shared__ float sc[Sz];
    __shared__ float red[8];
    int tid = threadIdx.x;
    int w = tid >> 5, l = tid & 31;
    for (int a = tid; a < Az; a += 256) s2s[a] = g_s2[b * Az + a];
    __syncthreads();
    for (int s = w; s < Sz; s += 8) {
        const float* row = g_s1 + ((size_t)s * Bz + b) * Az;
        float acc = 0.0f;
        for (int a = l; a < Az; a += 32) acc += tanhf(row[a] + s2s[a]) * Wv[a];
        for (int o = 16; o; o >>= 1) acc += __shfl_xor_sync(0xffffffffu, acc, o);
        if (l == 0) sc[s] = acc + bv[0];
    }
    __syncthreads();
    float m = -3.402823e38f;
    if (tid < Sz) m = sc[tid];
    for (int o = 16; o; o >>= 1) m = fmaxf(m, __shfl_xor_sync(0xffffffffu, m, o));
    if (l == 0) red[w] = m;
    __syncthreads();
    m = fmaxf(fmaxf(fmaxf(red[0], red[1]), fmaxf(red[2], red[3])),
              fmaxf(fmaxf(red[4], red[5]), fmaxf(red[6], red[7])));
    __syncthreads();
    float part = 0.0f;
    if (tid < Sz) { float e = expf(sc[tid] - m); sc[tid] = e; part = e; }
    for (int o = 16; o; o >>= 1) part += __shfl_xor_sync(0xffffffffu, part, o);
    if (l == 0) red[w] = part;
    __syncthreads();
    float inv = 1.0f / (red[0] + red[1] + red[2] + red[3] + red[4] + red[5] + red[6] + red[7]);
    for (int u = tid; u < Hz; u += 256) {
        float acc = 0.0f;
        for (int s = 0; s < Sz; s++) acc += sc[s] * g_enc[((size_t)s * Bz + b) * Hz + u];
        g_ctx[b * Hz + u] = acc * inv;
    }
}

// ---------------- argmax (first-occurrence tie-break) -----------------------------
__global__ void __launch_bounds__(256) k_argmax(const float* __restrict__ out, int t) {
    int b = blockIdx.x;
    const float* lg = out + (size_t)b * Tz * Vz + (size_t)t * Vz;
    int tid = threadIdx.x;
    float bm = -3.402823e38f;
    int bi = Vz;
    for (int v = tid; v < Vz; v += 256) {
        float x = lg[v];
        if (x > bm) { bm = x; bi = v; }
        else if (x == bm && v < bi) bi = v;
    }
    __shared__ float sv[256];
    __shared__ int si[256];
    sv[tid] = bm; si[tid] = bi;
    __syncthreads();
    for (int o = 128; o; o >>= 1) {
        if (tid < o) {
            if (sv[tid + o] > sv[tid] || (sv[tid + o] == sv[tid] && si[tid + o] < si[tid])) {
                sv[tid] = sv[tid + o]; si[tid] = si[tid + o];
            }
        }
        __syncthreads();
    }
    if (tid == 0) g_tok[b] = si[0];
}

// ---------------- host orchestration ---------------------------------------------
extern "C" void kernel_launch(void* const* d_in, const int* in_sizes, int n_in,
                              void* d_out, int out_size) {
    const int*   in_enc   = (const int*)d_in[0];
    const float* init_ctx = (const float*)d_in[1];
    const int*   in_dec   = (const int*)d_in[2];
    const float* emb_enc  = (const float*)d_in[3];
    const float* emb_dec  = (const float*)d_in[4];
    const float* Wih_e    = (const float*)d_in[5];
    const float* Whh_e    = (const float*)d_in[6];
    const float* bih_e    = (const float*)d_in[7];
    const float* bhh_e    = (const float*)d_in[8];
    const float* Wih_d    = (const float*)d_in[9];
    const float* Whh_d    = (const float*)d_in[10];
    const float* bih_d    = (const float*)d_in[11];
    const float* bhh_d    = (const float*)d_in[12];
    const float* We       = (const float*)d_in[13];
    const float* be       = (const float*)d_in[14];
    const float* Wd       = (const float*)d_in[15];
    const float* bd       = (const float*)d_in[16];
    const float* Wv       = (const float*)d_in[17];
    const float* bv       = (const float*)d_in[18];
    const float* Wout     = (const float*)d_in[19];
    const float* bout     = (const float*)d_in[20];
    float* out = (float*)d_out;

    float *pXg, *pEnc, *pS1, *pH, *pDconst, *pHd, *pS2, *pBeR, *pBdR;
    float *pWihRe, *pWhhRe, *pWihRd, *pWhhRd;
    cudaGetSymbolAddress((void**)&pXg, g_Xg);
    cudaGetSymbolAddress((void**)&pEnc, g_enc);
    cudaGetSymbolAddress((void**)&pS1, g_s1);
    cudaGetSymbolAddress((void**)&pH, g_h);
    cudaGetSymbolAddress((void**)&pDconst, g_dconst);
    cudaGetSymbolAddress((void**)&pHd, g_hd);
    cudaGetSymbolAddress((void**)&pS2, g_s2);
    cudaGetSymbolAddress((void**)&pBeR, g_beR);
    cudaGetSymbolAddress((void**)&pBdR, g_bdR);
    cudaGetSymbolAddress((void**)&pWihRe, g_WihRe);
    cudaGetSymbolAddress((void**)&pWhhRe, g_WhhRe);
    cudaGetSymbolAddress((void**)&pWihRd, g_WihRd);
    cudaGetSymbolAddress((void**)&pWhhRd, g_WhhRd);

    k_detect<<<1, 256>>>(in_enc, in_dec);
    k_init<<<256, 256>>>(bih_e, bhh_e, bih_d, bhh_d, init_ctx, in_dec);

    // one-time gate reorder
    k_reorder<<<G4, 128>>>(Wih_e, pWihRe, Hz);
    k_reorder<<<G4, 128>>>(Whh_e, pWhhRe, Hz);
    k_reorder<<<G4, 128>>>(Wih_d, pWihRd, 2 * Hz);
    k_reorder<<<G4, 128>>>(Whh_d, pWhhRd, Hz);

    // Xg = emb_enc[tok] @ WihRe^T + beR
    k_mm<1, 0><<<dim3(G4 / 32, (Sz * Bz) / 64), 128>>>(
        nullptr, 0, pWihRe, Hz, pBeR, nullptr, 0,
        pXg, G4, G4, Hz, in_enc, emb_enc, 0);

    // encoder recurrence: fused GEMM + LSTM cell per step
    for (int t = 0; t < Sz; t++) {
        k_mm<0, 2><<<dim3(G4 / 32, 1), 128>>>(
            pH, Hz, pWhhRe, Hz, nullptr, pXg + (size_t)t * Bz * G4, G4,
            nullptr, 0, G4, Hz, nullptr, nullptr, t);
    }

    // s1 = enc @ We^T + be
    k_mm<0, 0><<<dim3(Az / 32, (Sz * Bz) / 64), 128>>>(
        pEnc, Hz, We, Hz, be, nullptr, 0,
        pS1, Az, Az, Hz, nullptr, nullptr, 0);

    // decoder constant gates: hN @ WhhRd^T + bdR
    k_mm<0, 0><<<dim3(G4 / 32, 1), 128>>>(
        pH, Hz, pWhhRd, Hz, pBdR, nullptr, 0,
        pDconst, G4, G4, Hz, nullptr, nullptr, 0);

    // autoregressive decoder
    for (int t = 0; t < Tz; t++) {
        k_mm<2, 3><<<dim3(G4 / 32, 1), 128>>>(
            nullptr, 0, pWihRd, 2 * Hz, nullptr, pDconst, G4,
            nullptr, 0, G4, 2 * Hz, nullptr, emb_dec, 0);
        k_gemm32<<<dim3(Az / 32, 1), 128>>>(pHd, Hz, Wd, Hz, bd, pS2, Az, Az, Hz);
        k_attn<<<Bz, 256>>>(Wv, bv);
        k_mm<0, 0><<<dim3((Vz + 31) / 32, 1), 128>>>(
            pHd, Hz, Wout, Hz, bout, nullptr, 0,
            out + (size_t)t * Vz, Tz * Vz, Vz, Hz, nullptr, nullptr, 0);
        k_argmax<<<Bz, 256>>>(out, t);
    }
}